// round 12
// baseline (speedup 1.0000x reference)
#include <cuda_runtime.h>
#include <cuda_bf16.h>
#include <cstdint>
#include <stdint.h>

#define NN 100000
#define NE 600000
#define DI 128
#define DH 128
#define NC 64

// Scratch (device globals -- referenced ONLY inside kernels, never from host)
__device__ __align__(16) float g_nbr1[(size_t)NN * DI];   // layer-1 neighbor sums
__device__ __align__(16) float g_p[(size_t)NN * NC];      // h1 @ Wn2 (pre-projected)
__device__ __align__(16) float g_nbr2[(size_t)NN * NC];   // layer-2 neighbor sums
__device__ float g_deg[NN];                               // in-degree (float)
// h1 stored directly as bf16 hi/lo (written by gemm1 epilogue)
__device__ __align__(16) __nv_bfloat16 g_h1hi[(size_t)NN * DH];
__device__ __align__(16) __nv_bfloat16 g_h1lo[(size_t)NN * DH];
// Pre-converted layer-1 weights, B[n][k] = W[k][n], bf16 hi/lo, [ph][128n][128k]
__device__ __align__(16) __nv_bfloat16 g_B1hi[2 * 128 * 128];
__device__ __align__(16) __nv_bfloat16 g_B1lo[2 * 128 * 128];
// Pre-converted layer-2 weights: B2[n][k]; n<64 -> Ws2 col n, n>=64 -> Wn2 col n-64
__device__ __align__(16) __nv_bfloat16 g_B2hi[128 * 128];
__device__ __align__(16) __nv_bfloat16 g_B2lo[128 * 128];

// ---------------- HMMA helpers (baseline PTX, sm_80+, no 'a' target) ----
__device__ __forceinline__ uint32_t smem_to_u32(const void* p) {
    uint32_t a;
    asm("{ .reg .u64 t; cvta.to.shared.u64 t, %1; cvt.u32.u64 %0, t; }" : "=r"(a) : "l"(p));
    return a;
}
__device__ __forceinline__ void ldsm_x4(uint32_t* r, uint32_t addr) {
    asm volatile("ldmatrix.sync.aligned.m8n8.x4.shared.b16 {%0,%1,%2,%3}, [%4];"
                 : "=r"(r[0]), "=r"(r[1]), "=r"(r[2]), "=r"(r[3]) : "r"(addr));
}
__device__ __forceinline__ void mma_bf16(float* d, const uint32_t* a, const uint32_t* b) {
    asm volatile("mma.sync.aligned.m16n8k16.row.col.f32.bf16.bf16.f32 "
                 "{%0,%1,%2,%3}, {%4,%5,%6,%7}, {%8,%9}, {%0,%1,%2,%3};"
                 : "+f"(d[0]), "+f"(d[1]), "+f"(d[2]), "+f"(d[3])
                 : "r"(a[0]), "r"(a[1]), "r"(a[2]), "r"(a[3]), "r"(b[0]), "r"(b[1]));
}

// SMEM maps: rows padded to 136 bf16 (272B) -> conflict-free ldsm
#define RSTR 272
#define TILE_B (128 * RSTR)        // 34816 bytes per 128x128 bf16 tile
// gemm1: A_hi, A_lo, then 4 B tiles [ph][hi/lo]
#define SM_A_HI 0
#define SM_A_LO TILE_B
#define SM_B    (2 * TILE_B)
#define SMEM_MMA (6 * TILE_B)      // 208896 B
// gemm64: A_hi, A_lo, B_hi, B_lo
#define SM2_B   (2 * TILE_B)
#define SMEM_MMA2 (4 * TILE_B)     // 139264 B

// ---------------------------------------------------------------------------
__global__ void zero_kernel() {
    const int n1 = NN * DI / 4;
    const int n2 = NN * NC / 4;
    const int nd = NN / 4;
    int i = blockIdx.x * blockDim.x + threadIdx.x;
    float4 z = make_float4(0.f, 0.f, 0.f, 0.f);
    if (i < n1)                 ((float4*)g_nbr1)[i] = z;
    else if (i < n1 + n2)       ((float4*)g_nbr2)[i - n1] = z;
    else if (i < n1 + n2 + nd)  ((float4*)g_deg)[i - n1 - n2] = z;
}

// ---------------------------------------------------------------------------
// Pre-convert layer-1 weights: B1[ph][n][k] = W_ph[k][n], bf16 hi/lo
// ---------------------------------------------------------------------------
__global__ void convert_w1_kernel(const float* __restrict__ Ws1,
                                  const float* __restrict__ Wn1) {
    int i = blockIdx.x * blockDim.x + threadIdx.x;
    if (i >= 2 * 128 * 128) return;
    int ph = i >> 14, rem = i & 16383;
    int n = rem >> 7, k = rem & 127;
    const float* W = ph ? Wn1 : Ws1;
    float v = W[k * 128 + n];
    __nv_bfloat16 h = __float2bfloat16(v);
    __nv_bfloat16 l = __float2bfloat16(v - __bfloat162float(h));
    g_B1hi[i] = h;
    g_B1lo[i] = l;
}

// ---------------------------------------------------------------------------
// Pre-convert layer-2 weights: B2[n][k]; n<64 -> Ws2[k][n], n>=64 -> Wn2[k][n-64]
// ---------------------------------------------------------------------------
__global__ void convert_w2_kernel(const float* __restrict__ Ws2,
                                  const float* __restrict__ Wn2) {
    int i = blockIdx.x * blockDim.x + threadIdx.x;
    if (i >= 128 * 128) return;
    int n = i >> 7, k = i & 127;
    float v = (n < 64) ? Ws2[k * 64 + n] : Wn2[k * 64 + (n - 64)];
    __nv_bfloat16 h = __float2bfloat16(v);
    __nv_bfloat16 l = __float2bfloat16(v - __bfloat162float(h));
    g_B2hi[i] = h;
    g_B2lo[i] = l;
}

// ---------------------------------------------------------------------------
// Layer-1 edge scatter (proven): warp per edge, REDG.128 x32 + degree
// ---------------------------------------------------------------------------
__global__ void scatter1_kernel(const float* __restrict__ x,
                                const int* __restrict__ src,
                                const int* __restrict__ dst) {
    int gw = (blockIdx.x * blockDim.x + threadIdx.x) >> 5;
    if (gw >= NE) return;
    int lane = threadIdx.x & 31;
    int s = __ldg(src + gw);
    int d = __ldg(dst + gw);
    float4 v = ((const float4*)x)[(size_t)s * 32 + lane];
    float4* p = ((float4*)g_nbr1) + (size_t)d * 32 + lane;
    asm volatile("red.global.add.v4.f32 [%0], {%1, %2, %3, %4};"
                 :: "l"(p), "f"(v.x), "f"(v.y), "f"(v.z), "f"(v.w)
                 : "memory");
    if (lane == 0) atomicAdd(&g_deg[d], 1.0f);
}

// ---------------------------------------------------------------------------
// Layer-2 edge scatter of g_p (64-wide): HALF-warp per edge (proven)
// ---------------------------------------------------------------------------
__global__ void scatter2_kernel(const int* __restrict__ src,
                                const int* __restrict__ dst) {
    int gw = (blockIdx.x * blockDim.x + threadIdx.x) >> 5;
    int lane = threadIdx.x & 31;
    int e = gw * 2 + (lane >> 4);
    if (e >= NE) return;
    int l16 = lane & 15;
    int s = __ldg(src + e);
    int d = __ldg(dst + e);
    float4 v = ((const float4*)g_p)[(size_t)s * 16 + l16];
    float4* p = ((float4*)g_nbr2) + (size_t)d * 16 + l16;
    asm volatile("red.global.add.v4.f32 [%0], {%1, %2, %3, %4};"
                 :: "l"(p), "f"(v.x), "f"(v.y), "f"(v.z), "f"(v.w)
                 : "memory");
}

// ---------------------------------------------------------------------------
// Layer 1 via HMMA (PROVEN R11 shell): h1 = relu(x@Ws1 + (nbr1/deg)@Wn1 + b1)
// Epilogue change vs R11: store h1 as bf16 hi/lo pairs (g_h1hi/g_h1lo).
// ---------------------------------------------------------------------------
__global__ void __launch_bounds__(256)
gemm1_mma_kernel(const float* __restrict__ x,
                 const float* __restrict__ bias) {
    extern __shared__ char smem[];
    uint32_t smem_base = smem_to_u32(smem);
    int tid = threadIdx.x;
    int w = tid >> 5, l = tid & 31;
    int wm = w & 3, wn = w >> 2;

    // Preload all B tiles ([ph][hi/lo][128n][k], padded rows)
    {
        const uint32_t* hi32 = (const uint32_t*)g_B1hi;
        const uint32_t* lo32 = (const uint32_t*)g_B1lo;
        for (int i = tid; i < 32768; i += 256) {
            int kp = i & 63, n = (i >> 6) & 127, hilo = (i >> 13) & 1, ph = i >> 14;
            uint32_t v = (hilo ? lo32 : hi32)[ph * 8192 + n * 64 + kp];
            *(uint32_t*)(smem + SM_B + (ph * 2 + hilo) * TILE_B + n * RSTR + kp * 4) = v;
        }
    }

    int rowc = tid >> 1;               // A-convert row (0..127)
    int khalf = (tid & 1) << 6;        // feature half

    const int nTiles = (NN + 127) / 128;
    for (int tile = blockIdx.x; tile < nTiles; tile += gridDim.x) {
        int base = tile * 128;
        float acc[2][8][4];
        #pragma unroll
        for (int bm = 0; bm < 2; bm++)
            #pragma unroll
            for (int bn = 0; bn < 8; bn++)
                #pragma unroll
                for (int j = 0; j < 4; j++) acc[bm][bn][j] = 0.f;

        #pragma unroll
        for (int ph = 0; ph < 2; ++ph) {
            __syncthreads();
            {   // convert A tile: fp32 -> bf16 hi/lo rows [m][k]
                const float* feat = ph ? g_nbr1 : x;
                int node = base + rowc;
                bool valid = node < NN;
                float scale = 1.0f;
                if (ph && valid) scale = 1.0f / fmaxf(g_deg[node], 1.0f);
                const float4* rp = (const float4*)(feat + (size_t)node * DI + khalf);
                #pragma unroll
                for (int i = 0; i < 16; i++) {
                    float4 v = make_float4(0.f, 0.f, 0.f, 0.f);
                    if (valid) v = rp[i];
                    v.x *= scale; v.y *= scale; v.z *= scale; v.w *= scale;
                    int c = khalf + i * 4;
                    __nv_bfloat162 h01, l01, h23, l23;
                    h01.x = __float2bfloat16(v.x);
                    l01.x = __float2bfloat16(v.x - __bfloat162float(h01.x));
                    h01.y = __float2bfloat16(v.y);
                    l01.y = __float2bfloat16(v.y - __bfloat162float(h01.y));
                    h23.x = __float2bfloat16(v.z);
                    l23.x = __float2bfloat16(v.z - __bfloat162float(h23.x));
                    h23.y = __float2bfloat16(v.w);
                    l23.y = __float2bfloat16(v.w - __bfloat162float(h23.y));
                    uint32_t o = (uint32_t)(rowc * RSTR + c * 2);
                    *(__nv_bfloat162*)(smem + SM_A_HI + o)     = h01;
                    *(__nv_bfloat162*)(smem + SM_A_HI + o + 4) = h23;
                    *(__nv_bfloat162*)(smem + SM_A_LO + o)     = l01;
                    *(__nv_bfloat162*)(smem + SM_A_LO + o + 4) = l23;
                }
            }
            __syncthreads();

            uint32_t bb_hi = smem_base + SM_B + (uint32_t)(ph * 2) * TILE_B;
            #pragma unroll
            for (int s = 0; s < 8; s++) {
                int k0 = s << 4;
                uint32_t ahi[2][4], alo[2][4];
                #pragma unroll
                for (int bm = 0; bm < 2; bm++) {
                    int row = (wm << 5) + (bm << 4) + (l & 7) + (((l >> 3) & 1) << 3);
                    int col = k0 + ((l >> 4) << 3);
                    uint32_t ad = smem_base + (uint32_t)(row * RSTR + col * 2);
                    ldsm_x4(ahi[bm], ad + SM_A_HI);
                    ldsm_x4(alo[bm], ad + SM_A_LO);
                }
                uint32_t bhi[8][2], blo[8][2];
                #pragma unroll
                for (int t = 0; t < 4; t++) {
                    int row = (wn << 6) + (t << 4) + (l & 7) + ((l >> 4) << 3);
                    int col = k0 + (((l >> 3) & 1) << 3);
                    uint32_t bd = bb_hi + (uint32_t)(row * RSTR + col * 2);
                    uint32_t r[4];
                    ldsm_x4(r, bd);
                    bhi[2 * t][0] = r[0]; bhi[2 * t][1] = r[1];
                    bhi[2 * t + 1][0] = r[2]; bhi[2 * t + 1][1] = r[3];
                    ldsm_x4(r, bd + TILE_B);
                    blo[2 * t][0] = r[0]; blo[2 * t][1] = r[1];
                    blo[2 * t + 1][0] = r[2]; blo[2 * t + 1][1] = r[3];
                }
                #pragma unroll
                for (int bm = 0; bm < 2; bm++)
                    #pragma unroll
                    for (int bn = 0; bn < 8; bn++) {
                        mma_bf16(acc[bm][bn], ahi[bm], bhi[bn]);
                        mma_bf16(acc[bm][bn], ahi[bm], blo[bn]);
                        mma_bf16(acc[bm][bn], alo[bm], bhi[bn]);
                    }
            }
        }

        // Epilogue: bias + relu -> g_h1hi/g_h1lo (bf16 split pairs)
        #pragma unroll
        for (int bm = 0; bm < 2; bm++) {
            int r0 = base + (wm << 5) + (bm << 4) + (l >> 2);
            #pragma unroll
            for (int bn = 0; bn < 8; bn++) {
                int n = (wn << 6) + (bn << 3) + ((l & 3) << 1);
                float2 bv = *(const float2*)(bias + n);
                #pragma unroll
                for (int half = 0; half < 2; half++) {
                    int r = r0 + half * 8;
                    if (r < NN) {
                        float o0 = fmaxf(acc[bm][bn][2 * half + 0] + bv.x, 0.f);
                        float o1 = fmaxf(acc[bm][bn][2 * half + 1] + bv.y, 0.f);
                        __nv_bfloat162 h2, l2;
                        h2.x = __float2bfloat16(o0);
                        l2.x = __float2bfloat16(o0 - __bfloat162float(h2.x));
                        h2.y = __float2bfloat16(o1);
                        l2.y = __float2bfloat16(o1 - __bfloat162float(h2.y));
                        *(__nv_bfloat162*)(g_h1hi + (size_t)r * DH + n) = h2;
                        *(__nv_bfloat162*)(g_h1lo + (size_t)r * DH + n) = l2;
                    }
                }
            }
        }
    }
}

// ---------------------------------------------------------------------------
// Layer 2 via HMMA: one N=128 GEMM with B2 = [Ws2 | Wn2] transposed.
//   cols 0-63  (+b2) -> d_out ; cols 64-127 -> g_p
// A = h1 already in bf16 hi/lo (pure copy into SMEM). K=128, single phase.
// ---------------------------------------------------------------------------
__global__ void __launch_bounds__(256)
gemm2_mma_kernel(const float* __restrict__ bias,
                 float* __restrict__ out_ext) {
    extern __shared__ char smem[];
    uint32_t smem_base = smem_to_u32(smem);
    int tid = threadIdx.x;
    int w = tid >> 5, l = tid & 31;
    int wm = w & 3, wn = w >> 2;

    // Preload B2 hi/lo tiles
    {
        const uint32_t* hi32 = (const uint32_t*)g_B2hi;
        const uint32_t* lo32 = (const uint32_t*)g_B2lo;
        for (int i = tid; i < 16384; i += 256) {
            int kp = i & 63, n = (i >> 6) & 127, hilo = i >> 13;
            uint32_t v = (hilo ? lo32 : hi32)[n * 64 + kp];
            *(uint32_t*)(smem + SM2_B + hilo * TILE_B + n * RSTR + kp * 4) = v;
        }
    }

    int rowc = tid >> 1;               // A-copy row (0..127)
    int jh = (tid & 1) << 5;           // uint32 half (32 of 64 per row)

    const int nTiles = (NN + 127) / 128;
    for (int tile = blockIdx.x; tile < nTiles; tile += gridDim.x) {
        int base = tile * 128;
        float acc[2][8][4];
        #pragma unroll
        for (int bm = 0; bm < 2; bm++)
            #pragma unroll
            for (int bn = 0; bn < 8; bn++)
                #pragma unroll
                for (int j = 0; j < 4; j++) acc[bm][bn][j] = 0.f;

        __syncthreads();
        {   // copy A tile from g_h1hi/g_h1lo (bf16, no conversion)
            int node = base + rowc;
            bool valid = node < NN;
            const uint32_t* rh = (const uint32_t*)(g_h1hi + (size_t)node * DH);
            const uint32_t* rl = (const uint32_t*)(g_h1lo + (size_t)node * DH);
            #pragma unroll
            for (int j = 0; j < 32; j++) {
                uint32_t vh = 0, vl = 0;
                if (valid) { vh = rh[jh + j]; vl = rl[jh + j]; }
                uint32_t o = (uint32_t)(rowc * RSTR + (jh + j) * 4);
                *(uint32_t*)(smem + SM_A_HI + o) = vh;
                *(uint32_t*)(smem + SM_A_LO + o) = vl;
            }
        }
        __syncthreads();

        uint32_t bb_hi = smem_base + SM2_B;
        #pragma unroll
        for (int s = 0; s < 8; s++) {
            int k0 = s << 4;
            uint32_t ahi[2][4], alo[2][4];
            #pragma unroll
            for (int bm = 0; bm < 2; bm++) {
                int row = (wm << 5) + (bm << 4) + (l & 7) + (((l >> 3) & 1) << 3);
                int col = k0 + ((l >> 4) << 3);
                uint32_t ad = smem_base + (uint32_t)(row * RSTR + col * 2);
                ldsm_x4(ahi[bm], ad + SM_A_HI);
                ldsm_x4(alo[bm], ad + SM_A_LO);
            }
            uint32_t bhi[8][2], blo[8][2];
            #pragma unroll
            for (int t = 0; t < 4; t++) {
                int row = (wn << 6) + (t << 4) + (l & 7) + ((l >> 4) << 3);
                int col = k0 + (((l >> 3) & 1) << 3);
                uint32_t bd = bb_hi + (uint32_t)(row * RSTR + col * 2);
                uint32_t r[4];
                ldsm_x4(r, bd);
                bhi[2 * t][0] = r[0]; bhi[2 * t][1] = r[1];
                bhi[2 * t + 1][0] = r[2]; bhi[2 * t + 1][1] = r[3];
                ldsm_x4(r, bd + TILE_B);
                blo[2 * t][0] = r[0]; blo[2 * t][1] = r[1];
                blo[2 * t + 1][0] = r[2]; blo[2 * t + 1][1] = r[3];
            }
            #pragma unroll
            for (int bm = 0; bm < 2; bm++)
                #pragma unroll
                for (int bn = 0; bn < 8; bn++) {
                    mma_bf16(acc[bm][bn], ahi[bm], bhi[bn]);
                    mma_bf16(acc[bm][bn], ahi[bm], blo[bn]);
                    mma_bf16(acc[bm][bn], alo[bm], bhi[bn]);
                }
        }

        // Epilogue: wn==0 -> d_out cols 0-63 (+bias); wn==1 -> g_p cols 0-63
        #pragma unroll
        for (int bm = 0; bm < 2; bm++) {
            int r0 = base + (wm << 5) + (bm << 4) + (l >> 2);
            #pragma unroll
            for (int bn = 0; bn < 8; bn++) {
                int n = (wn << 6) + (bn << 3) + ((l & 3) << 1);
                #pragma unroll
                for (int half = 0; half < 2; half++) {
                    int r = r0 + half * 8;
                    if (r < NN) {
                        float o0 = acc[bm][bn][2 * half + 0];
                        float o1 = acc[bm][bn][2 * half + 1];
                        if (wn == 0) {
                            float2 bv = *(const float2*)(bias + n);
                            float2 o = make_float2(o0 + bv.x, o1 + bv.y);
                            *(float2*)(out_ext + (size_t)r * NC + n) = o;
                        } else {
                            float2 o = make_float2(o0, o1);
                            *(float2*)(g_p + (size_t)r * NC + (n - 64)) = o;
                        }
                    }
                }
            }
        }
    }
}

// ---------------------------------------------------------------------------
__global__ void final_kernel(float* __restrict__ out) {
    int i = blockIdx.x * blockDim.x + threadIdx.x;
    if (i >= NN * (NC / 4)) return;
    int node = i >> 4;
    float inv = 1.0f / fmaxf(g_deg[node], 1.0f);
    float4 nv = ((const float4*)g_nbr2)[i];
    float4 o = ((float4*)out)[i];
    o.x += nv.x * inv; o.y += nv.y * inv;
    o.z += nv.z * inv; o.w += nv.w * inv;
    ((float4*)out)[i] = o;
}

// ---------------------------------------------------------------------------
extern "C" void kernel_launch(void* const* d_in, const int* in_sizes, int n_in,
                              void* d_out, int out_size) {
    const float* x    = (const float*)d_in[0];
    const int*   src  = (const int*)d_in[1];
    const int*   dst  = (const int*)d_in[2];
    const float* Ws1  = (const float*)d_in[3];
    const float* Wn1  = (const float*)d_in[4];
    const float* b1   = (const float*)d_in[5];
    const float* Ws2  = (const float*)d_in[6];
    const float* Wn2  = (const float*)d_in[7];
    const float* b2   = (const float*)d_in[8];
    float* out = (float*)d_out;

    cudaFuncSetAttribute(gemm1_mma_kernel, cudaFuncAttributeMaxDynamicSharedMemorySize, SMEM_MMA);
    cudaFuncSetAttribute(gemm2_mma_kernel, cudaFuncAttributeMaxDynamicSharedMemorySize, SMEM_MMA2);

    // 1) zero accumulators + degree; pre-convert weights (independent)
    {
        int total4 = NN * DI / 4 + NN * NC / 4 + NN / 4;
        zero_kernel<<<(total4 + 255) / 256, 256>>>();
    }
    convert_w1_kernel<<<(2 * 128 * 128 + 255) / 256, 256>>>(Ws1, Wn1);
    convert_w2_kernel<<<(128 * 128 + 255) / 256, 256>>>(Ws2, Wn2);
    // 2) layer-1 scatter (+ degree)
    scatter1_kernel<<<(NE * 32 + 255) / 256, 256>>>(x, src, dst);
    // 3) layer-1 GEMM (HMMA) -> g_h1hi/g_h1lo (bf16 split)
    gemm1_mma_kernel<<<148, 256, SMEM_MMA>>>(x, b1);
    // 4) layer-2 dual GEMM (HMMA): d_out = h1@Ws2 + b2 ; g_p = h1@Wn2
    gemm2_mma_kernel<<<148, 256, SMEM_MMA2>>>(b2, out);
    // 5) layer-2 scatter of g_p
    scatter2_kernel<<<(NE / 2 * 32 + 255) / 256, 256>>>(src, dst);
    // 6) out += nbr2 / deg
    final_kernel<<<(NN * (NC / 4) + 255) / 256, 256>>>(out);
}

// round 13
// speedup vs baseline: 1.0902x; 1.0902x over previous
#include <cuda_runtime.h>
#include <cuda_bf16.h>
#include <cstdint>
#include <stdint.h>

#define NN 100000
#define NE 600000
#define DI 128
#define DH 128
#define NC 64

// Scratch (device globals -- referenced ONLY inside kernels, never from host)
__device__ __align__(16) float g_nbr1[(size_t)NN * DI];   // layer-1 neighbor sums
__device__ __align__(16) float g_p[(size_t)NN * NC];      // h1 @ Wn2 (pre-projected)
__device__ __align__(16) float g_nbr2[(size_t)NN * NC];   // layer-2 neighbor sums
__device__ float g_deg[NN];                               // in-degree (float)
// h1 stored directly as bf16 hi/lo (written by gemm1 epilogue)
__device__ __align__(16) __nv_bfloat16 g_h1hi[(size_t)NN * DH];
__device__ __align__(16) __nv_bfloat16 g_h1lo[(size_t)NN * DH];
// Pre-converted layer-1 weights, B[n][k] = W[k][n], bf16 hi/lo, [ph][128n][128k]
__device__ __align__(16) __nv_bfloat16 g_B1hi[2 * 128 * 128];
__device__ __align__(16) __nv_bfloat16 g_B1lo[2 * 128 * 128];
// Pre-converted layer-2 weights: B2[n][k]; n<64 -> Ws2 col n, n>=64 -> Wn2 col n-64
__device__ __align__(16) __nv_bfloat16 g_B2hi[128 * 128];
__device__ __align__(16) __nv_bfloat16 g_B2lo[128 * 128];

// ---------------- HMMA helpers (baseline PTX, sm_80+, no 'a' target) ----
__device__ __forceinline__ uint32_t smem_to_u32(const void* p) {
    uint32_t a;
    asm("{ .reg .u64 t; cvta.to.shared.u64 t, %1; cvt.u32.u64 %0, t; }" : "=r"(a) : "l"(p));
    return a;
}
__device__ __forceinline__ void ldsm_x4(uint32_t* r, uint32_t addr) {
    asm volatile("ldmatrix.sync.aligned.m8n8.x4.shared.b16 {%0,%1,%2,%3}, [%4];"
                 : "=r"(r[0]), "=r"(r[1]), "=r"(r[2]), "=r"(r[3]) : "r"(addr));
}
__device__ __forceinline__ void mma_bf16(float* d, const uint32_t* a, const uint32_t* b) {
    asm volatile("mma.sync.aligned.m16n8k16.row.col.f32.bf16.bf16.f32 "
                 "{%0,%1,%2,%3}, {%4,%5,%6,%7}, {%8,%9}, {%0,%1,%2,%3};"
                 : "+f"(d[0]), "+f"(d[1]), "+f"(d[2]), "+f"(d[3])
                 : "r"(a[0]), "r"(a[1]), "r"(a[2]), "r"(a[3]), "r"(b[0]), "r"(b[1]));
}

// SMEM maps: rows padded to 136 bf16 (272B) -> conflict-free ldsm
#define RSTR 272
#define TILE_B (128 * RSTR)        // 34816 bytes per 128x128 bf16 tile
// gemm1: A_hi, A_lo, then 4 B tiles [ph][hi/lo]
#define SM_A_HI 0
#define SM_A_LO TILE_B
#define SM_B    (2 * TILE_B)
#define SMEM_MMA (6 * TILE_B)      // 208896 B
// gemm2: A_hi, A_lo, B_hi, B_lo
#define SM2_B   (2 * TILE_B)
#define SMEM_MMA2 (4 * TILE_B)     // 139264 B

// ---------------------------------------------------------------------------
__global__ void zero_kernel() {
    const int n1 = NN * DI / 4;
    const int n2 = NN * NC / 4;
    const int nd = NN / 4;
    int i = blockIdx.x * blockDim.x + threadIdx.x;
    float4 z = make_float4(0.f, 0.f, 0.f, 0.f);
    if (i < n1)                 ((float4*)g_nbr1)[i] = z;
    else if (i < n1 + n2)       ((float4*)g_nbr2)[i - n1] = z;
    else if (i < n1 + n2 + nd)  ((float4*)g_deg)[i - n1 - n2] = z;
}

// ---------------------------------------------------------------------------
// Pre-convert layer-1 weights: B1[ph][n][k] = W_ph[k][n], bf16 hi/lo
// ---------------------------------------------------------------------------
__global__ void convert_w1_kernel(const float* __restrict__ Ws1,
                                  const float* __restrict__ Wn1) {
    int i = blockIdx.x * blockDim.x + threadIdx.x;
    if (i >= 2 * 128 * 128) return;
    int ph = i >> 14, rem = i & 16383;
    int n = rem >> 7, k = rem & 127;
    const float* W = ph ? Wn1 : Ws1;
    float v = W[k * 128 + n];
    __nv_bfloat16 h = __float2bfloat16(v);
    __nv_bfloat16 l = __float2bfloat16(v - __bfloat162float(h));
    g_B1hi[i] = h;
    g_B1lo[i] = l;
}

// ---------------------------------------------------------------------------
// Pre-convert layer-2 weights: B2[n][k]; n<64 -> Ws2[k][n], n>=64 -> Wn2[k][n-64]
// ---------------------------------------------------------------------------
__global__ void convert_w2_kernel(const float* __restrict__ Ws2,
                                  const float* __restrict__ Wn2) {
    int i = blockIdx.x * blockDim.x + threadIdx.x;
    if (i >= 128 * 128) return;
    int n = i >> 7, k = i & 127;
    float v = (n < 64) ? Ws2[k * 64 + n] : Wn2[k * 64 + (n - 64)];
    __nv_bfloat16 h = __float2bfloat16(v);
    __nv_bfloat16 l = __float2bfloat16(v - __bfloat162float(h));
    g_B2hi[i] = h;
    g_B2lo[i] = l;
}

// ---------------------------------------------------------------------------
// Layer-1 edge scatter (proven): warp per edge, REDG.128 x32 + degree
// ---------------------------------------------------------------------------
__global__ void scatter1_kernel(const float* __restrict__ x,
                                const int* __restrict__ src,
                                const int* __restrict__ dst) {
    int gw = (blockIdx.x * blockDim.x + threadIdx.x) >> 5;
    if (gw >= NE) return;
    int lane = threadIdx.x & 31;
    int s = __ldg(src + gw);
    int d = __ldg(dst + gw);
    float4 v = ((const float4*)x)[(size_t)s * 32 + lane];
    float4* p = ((float4*)g_nbr1) + (size_t)d * 32 + lane;
    asm volatile("red.global.add.v4.f32 [%0], {%1, %2, %3, %4};"
                 :: "l"(p), "f"(v.x), "f"(v.y), "f"(v.z), "f"(v.w)
                 : "memory");
    if (lane == 0) atomicAdd(&g_deg[d], 1.0f);
}

// ---------------------------------------------------------------------------
// Layer-2 edge scatter of g_p (64-wide): HALF-warp per edge (proven)
// ---------------------------------------------------------------------------
__global__ void scatter2_kernel(const int* __restrict__ src,
                                const int* __restrict__ dst) {
    int gw = (blockIdx.x * blockDim.x + threadIdx.x) >> 5;
    int lane = threadIdx.x & 31;
    int e = gw * 2 + (lane >> 4);
    if (e >= NE) return;
    int l16 = lane & 15;
    int s = __ldg(src + e);
    int d = __ldg(dst + e);
    float4 v = ((const float4*)g_p)[(size_t)s * 16 + l16];
    float4* p = ((float4*)g_nbr2) + (size_t)d * 16 + l16;
    asm volatile("red.global.add.v4.f32 [%0], {%1, %2, %3, %4};"
                 :: "l"(p), "f"(v.x), "f"(v.y), "f"(v.z), "f"(v.w)
                 : "memory");
}

// ---------------------------------------------------------------------------
// Layer 1 via HMMA, 512 threads = 16 warps (4 M-strips x 4 N-groups of 32).
//   h1 = relu(x@Ws1 + (nbr1/deg)@Wn1 + b1) -> stored bf16 hi/lo
// Same verified SMEM layout / fragment addressing as R11; per-warp N halves.
// ---------------------------------------------------------------------------
__global__ void __launch_bounds__(512)
gemm1_mma_kernel(const float* __restrict__ x,
                 const float* __restrict__ bias) {
    extern __shared__ char smem[];
    uint32_t smem_base = smem_to_u32(smem);
    int tid = threadIdx.x;
    int w = tid >> 5, l = tid & 31;
    int wm = w & 3, wn = w >> 2;       // wm: 32-row strip, wn: 32-col group

    // Preload all B tiles ([ph][hi/lo][128n][k], padded rows)
    {
        const uint32_t* hi32 = (const uint32_t*)g_B1hi;
        const uint32_t* lo32 = (const uint32_t*)g_B1lo;
        for (int i = tid; i < 32768; i += 512) {
            int kp = i & 63, n = (i >> 6) & 127, hilo = (i >> 13) & 1, ph = i >> 14;
            uint32_t v = (hilo ? lo32 : hi32)[ph * 8192 + n * 64 + kp];
            *(uint32_t*)(smem + SM_B + (ph * 2 + hilo) * TILE_B + n * RSTR + kp * 4) = v;
        }
    }

    int rowc = tid >> 2;               // A-convert row (0..127)
    int c0 = (tid & 3) << 5;           // feature quarter (32 floats)

    const int nTiles = (NN + 127) / 128;
    for (int tile = blockIdx.x; tile < nTiles; tile += gridDim.x) {
        int base = tile * 128;
        float acc[2][4][4];
        #pragma unroll
        for (int bm = 0; bm < 2; bm++)
            #pragma unroll
            for (int bn = 0; bn < 4; bn++)
                #pragma unroll
                for (int j = 0; j < 4; j++) acc[bm][bn][j] = 0.f;

        #pragma unroll
        for (int ph = 0; ph < 2; ++ph) {
            __syncthreads();
            {   // convert A tile: fp32 -> bf16 hi/lo rows [m][k]
                const float* feat = ph ? g_nbr1 : x;
                int node = base + rowc;
                bool valid = node < NN;
                float scale = 1.0f;
                if (ph && valid) scale = 1.0f / fmaxf(g_deg[node], 1.0f);
                const float4* rp = (const float4*)(feat + (size_t)node * DI + c0);
                #pragma unroll
                for (int i = 0; i < 8; i++) {
                    float4 v = make_float4(0.f, 0.f, 0.f, 0.f);
                    if (valid) v = rp[i];
                    v.x *= scale; v.y *= scale; v.z *= scale; v.w *= scale;
                    int c = c0 + i * 4;
                    __nv_bfloat162 h01, l01, h23, l23;
                    h01.x = __float2bfloat16(v.x);
                    l01.x = __float2bfloat16(v.x - __bfloat162float(h01.x));
                    h01.y = __float2bfloat16(v.y);
                    l01.y = __float2bfloat16(v.y - __bfloat162float(h01.y));
                    h23.x = __float2bfloat16(v.z);
                    l23.x = __float2bfloat16(v.z - __bfloat162float(h23.x));
                    h23.y = __float2bfloat16(v.w);
                    l23.y = __float2bfloat16(v.w - __bfloat162float(h23.y));
                    uint32_t o = (uint32_t)(rowc * RSTR + c * 2);
                    *(__nv_bfloat162*)(smem + SM_A_HI + o)     = h01;
                    *(__nv_bfloat162*)(smem + SM_A_HI + o + 4) = h23;
                    *(__nv_bfloat162*)(smem + SM_A_LO + o)     = l01;
                    *(__nv_bfloat162*)(smem + SM_A_LO + o + 4) = l23;
                }
            }
            __syncthreads();

            uint32_t bb_hi = smem_base + SM_B + (uint32_t)(ph * 2) * TILE_B;
            #pragma unroll
            for (int s = 0; s < 8; s++) {
                int k0 = s << 4;
                uint32_t ahi[2][4], alo[2][4];
                #pragma unroll
                for (int bm = 0; bm < 2; bm++) {
                    int row = (wm << 5) + (bm << 4) + (l & 7) + (((l >> 3) & 1) << 3);
                    int col = k0 + ((l >> 4) << 3);
                    uint32_t ad = smem_base + (uint32_t)(row * RSTR + col * 2);
                    ldsm_x4(ahi[bm], ad + SM_A_HI);
                    ldsm_x4(alo[bm], ad + SM_A_LO);
                }
                uint32_t bhi[4][2], blo[4][2];
                #pragma unroll
                for (int t = 0; t < 2; t++) {
                    int row = (wn << 5) + (t << 4) + (l & 7) + ((l >> 4) << 3);
                    int col = k0 + (((l >> 3) & 1) << 3);
                    uint32_t bd = bb_hi + (uint32_t)(row * RSTR + col * 2);
                    uint32_t r[4];
                    ldsm_x4(r, bd);
                    bhi[2 * t][0] = r[0]; bhi[2 * t][1] = r[1];
                    bhi[2 * t + 1][0] = r[2]; bhi[2 * t + 1][1] = r[3];
                    ldsm_x4(r, bd + TILE_B);
                    blo[2 * t][0] = r[0]; blo[2 * t][1] = r[1];
                    blo[2 * t + 1][0] = r[2]; blo[2 * t + 1][1] = r[3];
                }
                #pragma unroll
                for (int bm = 0; bm < 2; bm++)
                    #pragma unroll
                    for (int bn = 0; bn < 4; bn++) {
                        mma_bf16(acc[bm][bn], ahi[bm], bhi[bn]);
                        mma_bf16(acc[bm][bn], ahi[bm], blo[bn]);
                        mma_bf16(acc[bm][bn], alo[bm], bhi[bn]);
                    }
            }
        }

        // Epilogue: bias + relu -> g_h1hi/g_h1lo (bf16 split pairs)
        #pragma unroll
        for (int bm = 0; bm < 2; bm++) {
            int r0 = base + (wm << 5) + (bm << 4) + (l >> 2);
            #pragma unroll
            for (int bn = 0; bn < 4; bn++) {
                int n = (wn << 5) + (bn << 3) + ((l & 3) << 1);
                float2 bv = *(const float2*)(bias + n);
                #pragma unroll
                for (int half = 0; half < 2; half++) {
                    int r = r0 + half * 8;
                    if (r < NN) {
                        float o0 = fmaxf(acc[bm][bn][2 * half + 0] + bv.x, 0.f);
                        float o1 = fmaxf(acc[bm][bn][2 * half + 1] + bv.y, 0.f);
                        __nv_bfloat162 h2, l2;
                        h2.x = __float2bfloat16(o0);
                        l2.x = __float2bfloat16(o0 - __bfloat162float(h2.x));
                        h2.y = __float2bfloat16(o1);
                        l2.y = __float2bfloat16(o1 - __bfloat162float(h2.y));
                        *(__nv_bfloat162*)(g_h1hi + (size_t)r * DH + n) = h2;
                        *(__nv_bfloat162*)(g_h1lo + (size_t)r * DH + n) = l2;
                    }
                }
            }
        }
    }
}

// ---------------------------------------------------------------------------
// Layer 2 via HMMA, 512 threads: one N=128 GEMM with B2 = [Ws2 | Wn2]^T.
//   cols 0-63 (+b2) -> d_out ; cols 64-127 -> g_p
// A = h1 already in bf16 hi/lo (pure copy into SMEM). K=128, single phase.
// ---------------------------------------------------------------------------
__global__ void __launch_bounds__(512)
gemm2_mma_kernel(const float* __restrict__ bias,
                 float* __restrict__ out_ext) {
    extern __shared__ char smem[];
    uint32_t smem_base = smem_to_u32(smem);
    int tid = threadIdx.x;
    int w = tid >> 5, l = tid & 31;
    int wm = w & 3, wn = w >> 2;

    // Preload B2 hi/lo tiles
    {
        const uint32_t* hi32 = (const uint32_t*)g_B2hi;
        const uint32_t* lo32 = (const uint32_t*)g_B2lo;
        for (int i = tid; i < 16384; i += 512) {
            int kp = i & 63, n = (i >> 6) & 127, hilo = i >> 13;
            uint32_t v = (hilo ? lo32 : hi32)[n * 64 + kp];
            *(uint32_t*)(smem + SM2_B + hilo * TILE_B + n * RSTR + kp * 4) = v;
        }
    }

    int rowc = tid >> 2;               // A-copy row (0..127)
    int jh = (tid & 3) << 4;           // uint32 quarter (16 of 64 per row)

    const int nTiles = (NN + 127) / 128;
    for (int tile = blockIdx.x; tile < nTiles; tile += gridDim.x) {
        int base = tile * 128;
        float acc[2][4][4];
        #pragma unroll
        for (int bm = 0; bm < 2; bm++)
            #pragma unroll
            for (int bn = 0; bn < 4; bn++)
                #pragma unroll
                for (int j = 0; j < 4; j++) acc[bm][bn][j] = 0.f;

        __syncthreads();
        {   // copy A tile from g_h1hi/g_h1lo (bf16, no conversion)
            int node = base + rowc;
            bool valid = node < NN;
            const uint32_t* rh = (const uint32_t*)(g_h1hi + (size_t)node * DH);
            const uint32_t* rl = (const uint32_t*)(g_h1lo + (size_t)node * DH);
            #pragma unroll
            for (int j = 0; j < 16; j++) {
                uint32_t vh = 0, vl = 0;
                if (valid) { vh = rh[jh + j]; vl = rl[jh + j]; }
                uint32_t o = (uint32_t)(rowc * RSTR + (jh + j) * 4);
                *(uint32_t*)(smem + SM_A_HI + o) = vh;
                *(uint32_t*)(smem + SM_A_LO + o) = vl;
            }
        }
        __syncthreads();

        uint32_t bb_hi = smem_base + SM2_B;
        #pragma unroll
        for (int s = 0; s < 8; s++) {
            int k0 = s << 4;
            uint32_t ahi[2][4], alo[2][4];
            #pragma unroll
            for (int bm = 0; bm < 2; bm++) {
                int row = (wm << 5) + (bm << 4) + (l & 7) + (((l >> 3) & 1) << 3);
                int col = k0 + ((l >> 4) << 3);
                uint32_t ad = smem_base + (uint32_t)(row * RSTR + col * 2);
                ldsm_x4(ahi[bm], ad + SM_A_HI);
                ldsm_x4(alo[bm], ad + SM_A_LO);
            }
            uint32_t bhi[4][2], blo[4][2];
            #pragma unroll
            for (int t = 0; t < 2; t++) {
                int row = (wn << 5) + (t << 4) + (l & 7) + ((l >> 4) << 3);
                int col = k0 + (((l >> 3) & 1) << 3);
                uint32_t bd = bb_hi + (uint32_t)(row * RSTR + col * 2);
                uint32_t r[4];
                ldsm_x4(r, bd);
                bhi[2 * t][0] = r[0]; bhi[2 * t][1] = r[1];
                bhi[2 * t + 1][0] = r[2]; bhi[2 * t + 1][1] = r[3];
                ldsm_x4(r, bd + TILE_B);
                blo[2 * t][0] = r[0]; blo[2 * t][1] = r[1];
                blo[2 * t + 1][0] = r[2]; blo[2 * t + 1][1] = r[3];
            }
            #pragma unroll
            for (int bm = 0; bm < 2; bm++)
                #pragma unroll
                for (int bn = 0; bn < 4; bn++) {
                    mma_bf16(acc[bm][bn], ahi[bm], bhi[bn]);
                    mma_bf16(acc[bm][bn], ahi[bm], blo[bn]);
                    mma_bf16(acc[bm][bn], alo[bm], bhi[bn]);
                }
        }

        // Epilogue: n<64 -> d_out (+bias); n>=64 -> g_p (col n-64)
        #pragma unroll
        for (int bm = 0; bm < 2; bm++) {
            int r0 = base + (wm << 5) + (bm << 4) + (l >> 2);
            #pragma unroll
            for (int bn = 0; bn < 4; bn++) {
                int n = (wn << 5) + (bn << 3) + ((l & 3) << 1);
                #pragma unroll
                for (int half = 0; half < 2; half++) {
                    int r = r0 + half * 8;
                    if (r < NN) {
                        float o0 = acc[bm][bn][2 * half + 0];
                        float o1 = acc[bm][bn][2 * half + 1];
                        if (n < 64) {
                            float2 bv = *(const float2*)(bias + n);
                            float2 o = make_float2(o0 + bv.x, o1 + bv.y);
                            *(float2*)(out_ext + (size_t)r * NC + n) = o;
                        } else {
                            float2 o = make_float2(o0, o1);
                            *(float2*)(g_p + (size_t)r * NC + (n - 64)) = o;
                        }
                    }
                }
            }
        }
    }
}

// ---------------------------------------------------------------------------
__global__ void final_kernel(float* __restrict__ out) {
    int i = blockIdx.x * blockDim.x + threadIdx.x;
    if (i >= NN * (NC / 4)) return;
    int node = i >> 4;
    float inv = 1.0f / fmaxf(g_deg[node], 1.0f);
    float4 nv = ((const float4*)g_nbr2)[i];
    float4 o = ((float4*)out)[i];
    o.x += nv.x * inv; o.y += nv.y * inv;
    o.z += nv.z * inv; o.w += nv.w * inv;
    ((float4*)out)[i] = o;
}

// ---------------------------------------------------------------------------
extern "C" void kernel_launch(void* const* d_in, const int* in_sizes, int n_in,
                              void* d_out, int out_size) {
    const float* x    = (const float*)d_in[0];
    const int*   src  = (const int*)d_in[1];
    const int*   dst  = (const int*)d_in[2];
    const float* Ws1  = (const float*)d_in[3];
    const float* Wn1  = (const float*)d_in[4];
    const float* b1   = (const float*)d_in[5];
    const float* Ws2  = (const float*)d_in[6];
    const float* Wn2  = (const float*)d_in[7];
    const float* b2   = (const float*)d_in[8];
    float* out = (float*)d_out;

    cudaFuncSetAttribute(gemm1_mma_kernel, cudaFuncAttributeMaxDynamicSharedMemorySize, SMEM_MMA);
    cudaFuncSetAttribute(gemm2_mma_kernel, cudaFuncAttributeMaxDynamicSharedMemorySize, SMEM_MMA2);

    // 1) zero accumulators + degree; pre-convert weights (independent)
    {
        int total4 = NN * DI / 4 + NN * NC / 4 + NN / 4;
        zero_kernel<<<(total4 + 255) / 256, 256>>>();
    }
    convert_w1_kernel<<<(2 * 128 * 128 + 255) / 256, 256>>>(Ws1, Wn1);
    convert_w2_kernel<<<(128 * 128 + 255) / 256, 256>>>(Ws2, Wn2);
    // 2) layer-1 scatter (+ degree)
    scatter1_kernel<<<(NE * 32 + 255) / 256, 256>>>(x, src, dst);
    // 3) layer-1 GEMM (HMMA, 16 warps) -> g_h1hi/g_h1lo
    gemm1_mma_kernel<<<148, 512, SMEM_MMA>>>(x, b1);
    // 4) layer-2 dual GEMM (HMMA, 16 warps): d_out = h1@Ws2 + b2 ; g_p = h1@Wn2
    gemm2_mma_kernel<<<148, 512, SMEM_MMA2>>>(b2, out);
    // 5) layer-2 scatter of g_p
    scatter2_kernel<<<(NE / 2 * 32 + 255) / 256, 256>>>(src, dst);
    // 6) out += nbr2 / deg
    final_kernel<<<(NN * (NC / 4) + 255) / 256, 256>>>(out);
}

// round 14
// speedup vs baseline: 1.2302x; 1.1284x over previous
#include <cuda_runtime.h>
#include <cuda_bf16.h>
#include <cstdint>
#include <stdint.h>

#define NN 100000
#define NE 600000
#define DI 128
#define DH 128
#define NC 64
#define NBLK 98          // ceil(NN/1024)

// Scratch (device globals -- referenced ONLY inside kernels, never from host)
__device__ __align__(16) float g_nbr1[(size_t)NN * DI];   // layer-1 neighbor sums
__device__ __align__(16) float g_p[(size_t)NN * NC];      // h1 @ Wn2 (pre-projected)
__device__ float g_deg[NN];                               // in-degree (float)
// CSR (rebuilt every call)
__device__ int g_cnt[NN];
__device__ int g_rowptr[NN];
__device__ int g_cursor[NN];
__device__ int g_eidx[NE];
__device__ int g_blksum[128];
// h1 stored directly as bf16 hi/lo (written by gemm1 epilogue)
__device__ __align__(16) __nv_bfloat16 g_h1hi[(size_t)NN * DH];
__device__ __align__(16) __nv_bfloat16 g_h1lo[(size_t)NN * DH];
// Pre-converted layer-1 weights, B[n][k] = W[k][n], bf16 hi/lo, [ph][128n][128k]
__device__ __align__(16) __nv_bfloat16 g_B1hi[2 * 128 * 128];
__device__ __align__(16) __nv_bfloat16 g_B1lo[2 * 128 * 128];
// Pre-converted layer-2 weights: B2[n][k]; n<64 -> Ws2 col n, n>=64 -> Wn2 col n-64
__device__ __align__(16) __nv_bfloat16 g_B2hi[128 * 128];
__device__ __align__(16) __nv_bfloat16 g_B2lo[128 * 128];

// ---------------- HMMA helpers (baseline PTX, sm_80+, no 'a' target) ----
__device__ __forceinline__ uint32_t smem_to_u32(const void* p) {
    uint32_t a;
    asm("{ .reg .u64 t; cvta.to.shared.u64 t, %1; cvt.u32.u64 %0, t; }" : "=r"(a) : "l"(p));
    return a;
}
__device__ __forceinline__ void ldsm_x4(uint32_t* r, uint32_t addr) {
    asm volatile("ldmatrix.sync.aligned.m8n8.x4.shared.b16 {%0,%1,%2,%3}, [%4];"
                 : "=r"(r[0]), "=r"(r[1]), "=r"(r[2]), "=r"(r[3]) : "r"(addr));
}
__device__ __forceinline__ void mma_bf16(float* d, const uint32_t* a, const uint32_t* b) {
    asm volatile("mma.sync.aligned.m16n8k16.row.col.f32.bf16.bf16.f32 "
                 "{%0,%1,%2,%3}, {%4,%5,%6,%7}, {%8,%9}, {%0,%1,%2,%3};"
                 : "+f"(d[0]), "+f"(d[1]), "+f"(d[2]), "+f"(d[3])
                 : "r"(a[0]), "r"(a[1]), "r"(a[2]), "r"(a[3]), "r"(b[0]), "r"(b[1]));
}

// SMEM maps: rows padded to 136 bf16 (272B) -> conflict-free ldsm
#define RSTR 272
#define TILE_B (128 * RSTR)
#define SM_A_HI 0
#define SM_A_LO TILE_B
#define SM_B    (2 * TILE_B)
#define SMEM_MMA (6 * TILE_B)      // 208896 B
#define SM2_B   (2 * TILE_B)
#define SMEM_MMA2 (4 * TILE_B)     // 139264 B

// ================= CSR build =================
__global__ void zero_cnt_kernel() {
    int i = blockIdx.x * blockDim.x + threadIdx.x;
    if (i < NN) g_cnt[i] = 0;
}
__global__ void hist_kernel(const int* __restrict__ dst) {
    int e = blockIdx.x * blockDim.x + threadIdx.x;
    if (e < NE) atomicAdd(&g_cnt[__ldg(dst + e)], 1);
}
__global__ void scan1_kernel() {   // per-block exclusive scan of g_cnt
    __shared__ int s[1024];
    int t = threadIdx.x;
    int idx = blockIdx.x * 1024 + t;
    int v = (idx < NN) ? g_cnt[idx] : 0;
    s[t] = v;
    __syncthreads();
    for (int off = 1; off < 1024; off <<= 1) {
        int tmp = (t >= off) ? s[t - off] : 0;
        __syncthreads();
        s[t] += tmp;
        __syncthreads();
    }
    if (idx < NN) g_rowptr[idx] = s[t] - v;           // exclusive within block
    if (t == 1023) g_blksum[blockIdx.x] = s[t];       // block total
}
__global__ void scan2_kernel() {   // exclusive scan of 98 block sums
    __shared__ int s[128];
    int t = threadIdx.x;
    int v = (t < NBLK) ? g_blksum[t] : 0;
    s[t] = v;
    __syncthreads();
    for (int off = 1; off < 128; off <<= 1) {
        int tmp = (t >= off) ? s[t - off] : 0;
        __syncthreads();
        s[t] += tmp;
        __syncthreads();
    }
    if (t < NBLK) g_blksum[t] = s[t] - v;
}
__global__ void scan3_kernel() {   // add block offsets; init cursor; deg as float
    int i = blockIdx.x * blockDim.x + threadIdx.x;
    if (i >= NN) return;
    int rp = g_rowptr[i] + g_blksum[i >> 10];
    g_rowptr[i] = rp;
    g_cursor[i] = rp;
    g_deg[i] = (float)g_cnt[i];
}
__global__ void fill_kernel(const int* __restrict__ src, const int* __restrict__ dst) {
    int e = blockIdx.x * blockDim.x + threadIdx.x;
    if (e < NE) {
        int d = __ldg(dst + e);
        int pos = atomicAdd(&g_cursor[d], 1);
        g_eidx[pos] = __ldg(src + e);
    }
}

// ================= Gathers =================
// Layer 1: warp per node, nbr1[node] = sum over in-edges of x[src]
__global__ void gather1_kernel(const float* __restrict__ x) {
    int gw = (blockIdx.x * blockDim.x + threadIdx.x) >> 5;
    if (gw >= NN) return;
    int lane = threadIdx.x & 31;
    int beg = __ldg(g_rowptr + gw);
    int cnt = __ldg(g_cnt + gw);
    float4 acc = make_float4(0.f, 0.f, 0.f, 0.f);
    for (int i0 = 0; i0 < cnt; i0 += 32) {
        int m = min(32, cnt - i0);
        int myidx = (lane < m) ? __ldg(g_eidx + beg + i0 + lane) : 0;
        for (int j = 0; j < m; j++) {
            int s = __shfl_sync(0xffffffffu, myidx, j);
            float4 v = __ldg((const float4*)x + (size_t)s * 32 + lane);
            acc.x += v.x; acc.y += v.y; acc.z += v.z; acc.w += v.w;
        }
    }
    ((float4*)g_nbr1)[(size_t)gw * 32 + lane] = acc;
}

// Layer 2 (fused final): half-warp per node, out[node] += (sum g_p[src]) / deg
__global__ void gather2_kernel(float* __restrict__ out) {
    int gh = (blockIdx.x * blockDim.x + threadIdx.x) >> 4;
    if (gh >= NN) return;
    int l16 = threadIdx.x & 15;
    unsigned mask = 0xFFFFu << (threadIdx.x & 16);
    int beg = __ldg(g_rowptr + gh);
    int cnt = __ldg(g_cnt + gh);
    float4 acc = make_float4(0.f, 0.f, 0.f, 0.f);
    for (int i0 = 0; i0 < cnt; i0 += 16) {
        int m = min(16, cnt - i0);
        int myidx = (l16 < m) ? __ldg(g_eidx + beg + i0 + l16) : 0;
        for (int j = 0; j < m; j++) {
            int s = __shfl_sync(mask, myidx, j, 16);
            float4 v = __ldg((const float4*)g_p + (size_t)s * 16 + l16);
            acc.x += v.x; acc.y += v.y; acc.z += v.z; acc.w += v.w;
        }
    }
    float inv = 1.0f / fmaxf(g_deg[gh], 1.0f);
    float4 o = ((float4*)out)[(size_t)gh * 16 + l16];
    o.x += acc.x * inv; o.y += acc.y * inv;
    o.z += acc.z * inv; o.w += acc.w * inv;
    ((float4*)out)[(size_t)gh * 16 + l16] = o;
}

// ================= Weight pre-conversion =================
__global__ void convert_w1_kernel(const float* __restrict__ Ws1,
                                  const float* __restrict__ Wn1) {
    int i = blockIdx.x * blockDim.x + threadIdx.x;
    if (i >= 2 * 128 * 128) return;
    int ph = i >> 14, rem = i & 16383;
    int n = rem >> 7, k = rem & 127;
    const float* W = ph ? Wn1 : Ws1;
    float v = W[k * 128 + n];
    __nv_bfloat16 h = __float2bfloat16(v);
    __nv_bfloat16 l = __float2bfloat16(v - __bfloat162float(h));
    g_B1hi[i] = h;
    g_B1lo[i] = l;
}
__global__ void convert_w2_kernel(const float* __restrict__ Ws2,
                                  const float* __restrict__ Wn2) {
    int i = blockIdx.x * blockDim.x + threadIdx.x;
    if (i >= 128 * 128) return;
    int n = i >> 7, k = i & 127;
    float v = (n < 64) ? Ws2[k * 64 + n] : Wn2[k * 64 + (n - 64)];
    __nv_bfloat16 h = __float2bfloat16(v);
    __nv_bfloat16 l = __float2bfloat16(v - __bfloat162float(h));
    g_B2hi[i] = h;
    g_B2lo[i] = l;
}

// ---------------------------------------------------------------------------
// Layer 1 via HMMA, 512 threads (PROVEN R13): h1 = relu(x@Ws1 + (nbr1/deg)@Wn1 + b1)
// ---------------------------------------------------------------------------
__global__ void __launch_bounds__(512)
gemm1_mma_kernel(const float* __restrict__ x,
                 const float* __restrict__ bias) {
    extern __shared__ char smem[];
    uint32_t smem_base = smem_to_u32(smem);
    int tid = threadIdx.x;
    int w = tid >> 5, l = tid & 31;
    int wm = w & 3, wn = w >> 2;

    {
        const uint32_t* hi32 = (const uint32_t*)g_B1hi;
        const uint32_t* lo32 = (const uint32_t*)g_B1lo;
        for (int i = tid; i < 32768; i += 512) {
            int kp = i & 63, n = (i >> 6) & 127, hilo = (i >> 13) & 1, ph = i >> 14;
            uint32_t v = (hilo ? lo32 : hi32)[ph * 8192 + n * 64 + kp];
            *(uint32_t*)(smem + SM_B + (ph * 2 + hilo) * TILE_B + n * RSTR + kp * 4) = v;
        }
    }

    int rowc = tid >> 2;
    int c0 = (tid & 3) << 5;

    const int nTiles = (NN + 127) / 128;
    for (int tile = blockIdx.x; tile < nTiles; tile += gridDim.x) {
        int base = tile * 128;
        float acc[2][4][4];
        #pragma unroll
        for (int bm = 0; bm < 2; bm++)
            #pragma unroll
            for (int bn = 0; bn < 4; bn++)
                #pragma unroll
                for (int j = 0; j < 4; j++) acc[bm][bn][j] = 0.f;

        #pragma unroll
        for (int ph = 0; ph < 2; ++ph) {
            __syncthreads();
            {
                const float* feat = ph ? g_nbr1 : x;
                int node = base + rowc;
                bool valid = node < NN;
                float scale = 1.0f;
                if (ph && valid) scale = 1.0f / fmaxf(g_deg[node], 1.0f);
                const float4* rp = (const float4*)(feat + (size_t)node * DI + c0);
                #pragma unroll
                for (int i = 0; i < 8; i++) {
                    float4 v = make_float4(0.f, 0.f, 0.f, 0.f);
                    if (valid) v = rp[i];
                    v.x *= scale; v.y *= scale; v.z *= scale; v.w *= scale;
                    int c = c0 + i * 4;
                    __nv_bfloat162 h01, l01, h23, l23;
                    h01.x = __float2bfloat16(v.x);
                    l01.x = __float2bfloat16(v.x - __bfloat162float(h01.x));
                    h01.y = __float2bfloat16(v.y);
                    l01.y = __float2bfloat16(v.y - __bfloat162float(h01.y));
                    h23.x = __float2bfloat16(v.z);
                    l23.x = __float2bfloat16(v.z - __bfloat162float(h23.x));
                    h23.y = __float2bfloat16(v.w);
                    l23.y = __float2bfloat16(v.w - __bfloat162float(h23.y));
                    uint32_t o = (uint32_t)(rowc * RSTR + c * 2);
                    *(__nv_bfloat162*)(smem + SM_A_HI + o)     = h01;
                    *(__nv_bfloat162*)(smem + SM_A_HI + o + 4) = h23;
                    *(__nv_bfloat162*)(smem + SM_A_LO + o)     = l01;
                    *(__nv_bfloat162*)(smem + SM_A_LO + o + 4) = l23;
                }
            }
            __syncthreads();

            uint32_t bb_hi = smem_base + SM_B + (uint32_t)(ph * 2) * TILE_B;
            #pragma unroll
            for (int s = 0; s < 8; s++) {
                int k0 = s << 4;
                uint32_t ahi[2][4], alo[2][4];
                #pragma unroll
                for (int bm = 0; bm < 2; bm++) {
                    int row = (wm << 5) + (bm << 4) + (l & 7) + (((l >> 3) & 1) << 3);
                    int col = k0 + ((l >> 4) << 3);
                    uint32_t ad = smem_base + (uint32_t)(row * RSTR + col * 2);
                    ldsm_x4(ahi[bm], ad + SM_A_HI);
                    ldsm_x4(alo[bm], ad + SM_A_LO);
                }
                uint32_t bhi[4][2], blo[4][2];
                #pragma unroll
                for (int t = 0; t < 2; t++) {
                    int row = (wn << 5) + (t << 4) + (l & 7) + ((l >> 4) << 3);
                    int col = k0 + (((l >> 3) & 1) << 3);
                    uint32_t bd = bb_hi + (uint32_t)(row * RSTR + col * 2);
                    uint32_t r[4];
                    ldsm_x4(r, bd);
                    bhi[2 * t][0] = r[0]; bhi[2 * t][1] = r[1];
                    bhi[2 * t + 1][0] = r[2]; bhi[2 * t + 1][1] = r[3];
                    ldsm_x4(r, bd + TILE_B);
                    blo[2 * t][0] = r[0]; blo[2 * t][1] = r[1];
                    blo[2 * t + 1][0] = r[2]; blo[2 * t + 1][1] = r[3];
                }
                #pragma unroll
                for (int bm = 0; bm < 2; bm++)
                    #pragma unroll
                    for (int bn = 0; bn < 4; bn++) {
                        mma_bf16(acc[bm][bn], ahi[bm], bhi[bn]);
                        mma_bf16(acc[bm][bn], ahi[bm], blo[bn]);
                        mma_bf16(acc[bm][bn], alo[bm], bhi[bn]);
                    }
            }
        }

        #pragma unroll
        for (int bm = 0; bm < 2; bm++) {
            int r0 = base + (wm << 5) + (bm << 4) + (l >> 2);
            #pragma unroll
            for (int bn = 0; bn < 4; bn++) {
                int n = (wn << 5) + (bn << 3) + ((l & 3) << 1);
                float2 bv = *(const float2*)(bias + n);
                #pragma unroll
                for (int half = 0; half < 2; half++) {
                    int r = r0 + half * 8;
                    if (r < NN) {
                        float o0 = fmaxf(acc[bm][bn][2 * half + 0] + bv.x, 0.f);
                        float o1 = fmaxf(acc[bm][bn][2 * half + 1] + bv.y, 0.f);
                        __nv_bfloat162 h2, l2;
                        h2.x = __float2bfloat16(o0);
                        l2.x = __float2bfloat16(o0 - __bfloat162float(h2.x));
                        h2.y = __float2bfloat16(o1);
                        l2.y = __float2bfloat16(o1 - __bfloat162float(h2.y));
                        *(__nv_bfloat162*)(g_h1hi + (size_t)r * DH + n) = h2;
                        *(__nv_bfloat162*)(g_h1lo + (size_t)r * DH + n) = l2;
                    }
                }
            }
        }
    }
}

// ---------------------------------------------------------------------------
// Layer 2 via HMMA, 512 threads (PROVEN R13): N=128 GEMM, B2 = [Ws2 | Wn2]^T
//   cols 0-63 (+b2) -> d_out ; cols 64-127 -> g_p
// ---------------------------------------------------------------------------
__global__ void __launch_bounds__(512)
gemm2_mma_kernel(const float* __restrict__ bias,
                 float* __restrict__ out_ext) {
    extern __shared__ char smem[];
    uint32_t smem_base = smem_to_u32(smem);
    int tid = threadIdx.x;
    int w = tid >> 5, l = tid & 31;
    int wm = w & 3, wn = w >> 2;

    {
        const uint32_t* hi32 = (const uint32_t*)g_B2hi;
        const uint32_t* lo32 = (const uint32_t*)g_B2lo;
        for (int i = tid; i < 16384; i += 512) {
            int kp = i & 63, n = (i >> 6) & 127, hilo = i >> 13;
            uint32_t v = (hilo ? lo32 : hi32)[n * 64 + kp];
            *(uint32_t*)(smem + SM2_B + hilo * TILE_B + n * RSTR + kp * 4) = v;
        }
    }

    int rowc = tid >> 2;
    int jh = (tid & 3) << 4;

    const int nTiles = (NN + 127) / 128;
    for (int tile = blockIdx.x; tile < nTiles; tile += gridDim.x) {
        int base = tile * 128;
        float acc[2][4][4];
        #pragma unroll
        for (int bm = 0; bm < 2; bm++)
            #pragma unroll
            for (int bn = 0; bn < 4; bn++)
                #pragma unroll
                for (int j = 0; j < 4; j++) acc[bm][bn][j] = 0.f;

        __syncthreads();
        {
            int node = base + rowc;
            bool valid = node < NN;
            const uint32_t* rh = (const uint32_t*)(g_h1hi + (size_t)node * DH);
            const uint32_t* rl = (const uint32_t*)(g_h1lo + (size_t)node * DH);
            #pragma unroll
            for (int j = 0; j < 16; j++) {
                uint32_t vh = 0, vl = 0;
                if (valid) { vh = rh[jh + j]; vl = rl[jh + j]; }
                uint32_t o = (uint32_t)(rowc * RSTR + (jh + j) * 4);
                *(uint32_t*)(smem + SM_A_HI + o) = vh;
                *(uint32_t*)(smem + SM_A_LO + o) = vl;
            }
        }
        __syncthreads();

        uint32_t bb_hi = smem_base + SM2_B;
        #pragma unroll
        for (int s = 0; s < 8; s++) {
            int k0 = s << 4;
            uint32_t ahi[2][4], alo[2][4];
            #pragma unroll
            for (int bm = 0; bm < 2; bm++) {
                int row = (wm << 5) + (bm << 4) + (l & 7) + (((l >> 3) & 1) << 3);
                int col = k0 + ((l >> 4) << 3);
                uint32_t ad = smem_base + (uint32_t)(row * RSTR + col * 2);
                ldsm_x4(ahi[bm], ad + SM_A_HI);
                ldsm_x4(alo[bm], ad + SM_A_LO);
            }
            uint32_t bhi[4][2], blo[4][2];
            #pragma unroll
            for (int t = 0; t < 2; t++) {
                int row = (wn << 5) + (t << 4) + (l & 7) + ((l >> 4) << 3);
                int col = k0 + (((l >> 3) & 1) << 3);
                uint32_t bd = bb_hi + (uint32_t)(row * RSTR + col * 2);
                uint32_t r[4];
                ldsm_x4(r, bd);
                bhi[2 * t][0] = r[0]; bhi[2 * t][1] = r[1];
                bhi[2 * t + 1][0] = r[2]; bhi[2 * t + 1][1] = r[3];
                ldsm_x4(r, bd + TILE_B);
                blo[2 * t][0] = r[0]; blo[2 * t][1] = r[1];
                blo[2 * t + 1][0] = r[2]; blo[2 * t + 1][1] = r[3];
            }
            #pragma unroll
            for (int bm = 0; bm < 2; bm++)
                #pragma unroll
                for (int bn = 0; bn < 4; bn++) {
                    mma_bf16(acc[bm][bn], ahi[bm], bhi[bn]);
                    mma_bf16(acc[bm][bn], ahi[bm], blo[bn]);
                    mma_bf16(acc[bm][bn], alo[bm], bhi[bn]);
                }
        }

        #pragma unroll
        for (int bm = 0; bm < 2; bm++) {
            int r0 = base + (wm << 5) + (bm << 4) + (l >> 2);
            #pragma unroll
            for (int bn = 0; bn < 4; bn++) {
                int n = (wn << 5) + (bn << 3) + ((l & 3) << 1);
                #pragma unroll
                for (int half = 0; half < 2; half++) {
                    int r = r0 + half * 8;
                    if (r < NN) {
                        float o0 = acc[bm][bn][2 * half + 0];
                        float o1 = acc[bm][bn][2 * half + 1];
                        if (n < 64) {
                            float2 bv = *(const float2*)(bias + n);
                            float2 o = make_float2(o0 + bv.x, o1 + bv.y);
                            *(float2*)(out_ext + (size_t)r * NC + n) = o;
                        } else {
                            float2 o = make_float2(o0, o1);
                            *(float2*)(g_p + (size_t)r * NC + (n - 64)) = o;
                        }
                    }
                }
            }
        }
    }
}

// ---------------------------------------------------------------------------
extern "C" void kernel_launch(void* const* d_in, const int* in_sizes, int n_in,
                              void* d_out, int out_size) {
    const float* x    = (const float*)d_in[0];
    const int*   src  = (const int*)d_in[1];
    const int*   dst  = (const int*)d_in[2];
    const float* Ws1  = (const float*)d_in[3];
    const float* Wn1  = (const float*)d_in[4];
    const float* b1   = (const float*)d_in[5];
    const float* Ws2  = (const float*)d_in[6];
    const float* Wn2  = (const float*)d_in[7];
    const float* b2   = (const float*)d_in[8];
    float* out = (float*)d_out;

    cudaFuncSetAttribute(gemm1_mma_kernel, cudaFuncAttributeMaxDynamicSharedMemorySize, SMEM_MMA);
    cudaFuncSetAttribute(gemm2_mma_kernel, cudaFuncAttributeMaxDynamicSharedMemorySize, SMEM_MMA2);

    // Weight pre-conversion (independent of graph build)
    convert_w1_kernel<<<(2 * 128 * 128 + 255) / 256, 256>>>(Ws1, Wn1);
    convert_w2_kernel<<<(128 * 128 + 255) / 256, 256>>>(Ws2, Wn2);

    // CSR build
    zero_cnt_kernel<<<(NN + 255) / 256, 256>>>();
    hist_kernel<<<(NE + 255) / 256, 256>>>(dst);
    scan1_kernel<<<NBLK, 1024>>>();
    scan2_kernel<<<1, 128>>>();
    scan3_kernel<<<(NN + 255) / 256, 256>>>();
    fill_kernel<<<(NE + 255) / 256, 256>>>(src, dst);

    // Layer 1: gather + GEMM
    gather1_kernel<<<(NN * 32 + 255) / 256, 256>>>(x);
    gemm1_mma_kernel<<<148, 512, SMEM_MMA>>>(x, b1);

    // Layer 2: dual GEMM, then gather of g_p fused with final add
    gemm2_mma_kernel<<<148, 512, SMEM_MMA2>>>(b2, out);
    gather2_kernel<<<(NN * 16 + 255) / 256, 256>>>(out);
}